// round 1
// baseline (speedup 1.0000x reference)
#include <cuda_runtime.h>
#include <cstdint>

#define Bn 8
#define Cn 256
#define Pn 1024
#define HEADS 8
#define HD 32

// ---- scratch (static device globals; no allocation at runtime) ----
__device__ float g_q  [Bn*Cn*Pn];   // q projection           (B,256,1024)
__device__ float g_h1 [Bn*128*Pn];  // conv3x3+relu hidden    (B,128,1024)
__device__ float g_off[Bn*2*Pn];    // (ox,oy)*0.1 per pixel  (B,2,1024)
__device__ float g_kvs[Bn*Cn*Pn];   // bilinear-sampled kv    (B,256,1024)
__device__ float g_k  [Bn*Cn*Pn];
__device__ float g_v  [Bn*Cn*Pn];
__device__ float g_ao [Bn*Cn*Pn];   // attention output       (B,256,1024)

// =====================================================================
// Batched GEMM: Y[b,o,p] = sum_c W[o,c] * X[b,c,p]  (+ optional bias)
// O = gridDim.y*64, P = 1024, Cin passed in. 64x64 tile, 4x4 micro-tile.
// =====================================================================
__global__ void __launch_bounds__(256) gemm_kernel(
    const float* __restrict__ W, const float* __restrict__ X,
    const float* __restrict__ bias, float* __restrict__ Y, int Cin)
{
    __shared__ __align__(16) float sW[16][68];
    __shared__ __align__(16) float sX[16][68];
    const int b  = blockIdx.z;
    const int o0 = blockIdx.y * 64;
    const int p0 = blockIdx.x * 64;
    const int O  = gridDim.y * 64;
    const float* Xb = X + (size_t)b * Cin * Pn;
    float*       Yb = Y + (size_t)b * O   * Pn;
    const int tid = threadIdx.x;
    const int tr  = tid >> 4;   // 0..15 (o groups of 4)
    const int tc  = tid & 15;   // 0..15 (p groups of 4)

    float acc[4][4] = {};
    for (int c0 = 0; c0 < Cin; c0 += 16) {
        #pragma unroll
        for (int k = tid; k < 1024; k += 256) {
            int cc = k & 15, oo = k >> 4;
            sW[cc][oo] = W[(size_t)(o0 + oo) * Cin + c0 + cc];
        }
        {
            int c4 = tid >> 4, p4 = tid & 15;  // 16c x 16 float4
            float4 xv = *reinterpret_cast<const float4*>(
                Xb + (size_t)(c0 + c4) * Pn + p0 + p4 * 4);
            *reinterpret_cast<float4*>(&sX[c4][p4 * 4]) = xv;
        }
        __syncthreads();
        #pragma unroll
        for (int cc = 0; cc < 16; cc++) {
            float4 wv = *reinterpret_cast<const float4*>(&sW[cc][tr * 4]);
            float4 xv = *reinterpret_cast<const float4*>(&sX[cc][tc * 4]);
            float w[4] = {wv.x, wv.y, wv.z, wv.w};
            float x[4] = {xv.x, xv.y, xv.z, xv.w};
            #pragma unroll
            for (int i = 0; i < 4; i++)
                #pragma unroll
                for (int j = 0; j < 4; j++)
                    acc[i][j] += w[i] * x[j];
        }
        __syncthreads();
    }
    #pragma unroll
    for (int i = 0; i < 4; i++) {
        int o = o0 + tr * 4 + i;
        float bv = bias ? bias[o] : 0.0f;
        float4 r = make_float4(acc[i][0] + bv, acc[i][1] + bv,
                               acc[i][2] + bv, acc[i][3] + bv);
        *reinterpret_cast<float4*>(Yb + (size_t)o * Pn + p0 + tc * 4) = r;
    }
}

// =====================================================================
// Conv3x3 SAME (zero pad) + bias + relu as implicit GEMM:
//   h1[b,o,p] = relu( sum_{k<2304} Woff1[o,k] * Xshift[b,k,p] + boff1[o] )
// where k = c*9 + t, t = ky*3+kx, Xshift gathers g_q with spatial shift.
// O = 128. grid (16, 2, 8).
// =====================================================================
__global__ void __launch_bounds__(256) conv_kernel(
    const float* __restrict__ W, const float* __restrict__ bias)
{
    __shared__ __align__(16) float sW[16][68];
    __shared__ __align__(16) float sX[16][68];
    const int b  = blockIdx.z;
    const int o0 = blockIdx.y * 64;
    const int p0 = blockIdx.x * 64;
    const float* Xb = g_q  + (size_t)b * Cn  * Pn;
    float*       Yb = g_h1 + (size_t)b * 128 * Pn;
    const int tid = threadIdx.x;
    const int tr  = tid >> 4;
    const int tc  = tid & 15;

    float acc[4][4] = {};
    for (int c0 = 0; c0 < 2304; c0 += 16) {
        #pragma unroll
        for (int k = tid; k < 1024; k += 256) {
            int cc = k & 15, oo = k >> 4;
            sW[cc][oo] = W[(size_t)(o0 + oo) * 2304 + c0 + cc];
        }
        #pragma unroll
        for (int k = tid; k < 1024; k += 256) {
            int pp = k & 63, cc = k >> 6;
            int kk = c0 + cc;
            int c  = kk / 9;
            int t  = kk - c * 9;
            int p  = p0 + pp;
            int y  = (p >> 5) + (t / 3) - 1;
            int x  = (p & 31) + (t % 3) - 1;
            float v = 0.0f;
            if ((unsigned)y < 32u && (unsigned)x < 32u)
                v = Xb[(size_t)c * Pn + (y << 5) + x];
            sX[cc][pp] = v;
        }
        __syncthreads();
        #pragma unroll
        for (int cc = 0; cc < 16; cc++) {
            float4 wv = *reinterpret_cast<const float4*>(&sW[cc][tr * 4]);
            float4 xv = *reinterpret_cast<const float4*>(&sX[cc][tc * 4]);
            float w[4] = {wv.x, wv.y, wv.z, wv.w};
            float x[4] = {xv.x, xv.y, xv.z, xv.w};
            #pragma unroll
            for (int i = 0; i < 4; i++)
                #pragma unroll
                for (int j = 0; j < 4; j++)
                    acc[i][j] += w[i] * x[j];
        }
        __syncthreads();
    }
    #pragma unroll
    for (int i = 0; i < 4; i++) {
        int o = o0 + tr * 4 + i;
        float bv = bias[o];
        float4 r;
        r.x = fmaxf(acc[i][0] + bv, 0.0f);
        r.y = fmaxf(acc[i][1] + bv, 0.0f);
        r.z = fmaxf(acc[i][2] + bv, 0.0f);
        r.w = fmaxf(acc[i][3] + bv, 0.0f);
        *reinterpret_cast<float4*>(Yb + (size_t)o * Pn + p0 + tc * 4) = r;
    }
}

// =====================================================================
// Offsets: only rows 0,1 of Woff2 are used by the reference.
// ox = 0.1*(Woff2[0,:].h1 + boff2[0]); oy likewise with row 1.
// grid (4, 8), 256 threads.
// =====================================================================
__global__ void __launch_bounds__(256) offs_kernel(
    const float* __restrict__ Woff2, const float* __restrict__ boff2)
{
    const int b = blockIdx.y;
    const int p = blockIdx.x * 256 + threadIdx.x;
    const float* h1b = g_h1 + (size_t)b * 128 * Pn;
    float ox = boff2[0], oy = boff2[1];
    #pragma unroll 4
    for (int c = 0; c < 128; c++) {
        float h = h1b[(size_t)c * Pn + p];
        ox += Woff2[c]       * h;
        oy += Woff2[128 + c] * h;
    }
    g_off[((size_t)b * 2 + 0) * Pn + p] = ox * 0.1f;
    g_off[((size_t)b * 2 + 1) * Pn + p] = oy * 0.1f;
}

// =====================================================================
// Bilinear grid sample, border padding, align_corners=True.
// grid (4, 8, 8): z = channel group of 32.
// =====================================================================
__global__ void __launch_bounds__(256) samp_kernel(const float* __restrict__ kv)
{
    const int b  = blockIdx.y;
    const int p  = blockIdx.x * 256 + threadIdx.x;
    const int c0 = blockIdx.z * 32;
    float ox = g_off[((size_t)b * 2 + 0) * Pn + p];
    float oy = g_off[((size_t)b * 2 + 1) * Pn + p];
    int px = p & 31, py = p >> 5;
    float gx = -1.0f + px * (2.0f / 31.0f);
    float gy = -1.0f + py * (2.0f / 31.0f);
    float x = (gx + ox + 1.0f) * 0.5f * 31.0f;
    float y = (gy + oy + 1.0f) * 0.5f * 31.0f;
    x = fminf(fmaxf(x, 0.0f), 31.0f);
    y = fminf(fmaxf(y, 0.0f), 31.0f);
    float x0f = floorf(x), y0f = floorf(y);
    float wx = x - x0f, wy = y - y0f;
    int x0 = (int)x0f, y0 = (int)y0f;
    int x1 = min(x0 + 1, 31), y1 = min(y0 + 1, 31);
    float w00 = (1.0f - wx) * (1.0f - wy);
    float w01 = wx * (1.0f - wy);
    float w10 = (1.0f - wx) * wy;
    float w11 = wx * wy;
    int i00 = (y0 << 5) + x0, i01 = (y0 << 5) + x1;
    int i10 = (y1 << 5) + x0, i11 = (y1 << 5) + x1;
    const float* kvb = kv    + (size_t)b * Cn * Pn;
    float*       ob  = g_kvs + (size_t)b * Cn * Pn;
    #pragma unroll 4
    for (int c = c0; c < c0 + 32; c++) {
        const float* pl = kvb + (size_t)c * Pn;
        ob[(size_t)c * Pn + p] =
            w00 * pl[i00] + w01 * pl[i01] + w10 * pl[i10] + w11 * pl[i11];
    }
}

// =====================================================================
// Flash attention per (b,h): q,k,v are (1024 rows x 32 d) slices of the
// channel-major tensors. 128 threads, 2 q-rows/thread (qtile=256),
// K/V tiles of 16 rows in smem, float4 smem reads. grid (4, 64).
// =====================================================================
__global__ void __launch_bounds__(128, 2) attn_kernel()
{
    const int bh = blockIdx.y;           // b*8 + h
    const int b  = bh >> 3, h = bh & 7;
    const int p0 = blockIdx.x * 256;
    const int tid = threadIdx.x;
    const int r0 = p0 + tid, r1 = r0 + 128;
    const float scale = 0.17677669529663687f;  // 1/sqrt(32)
    const float* qb = g_q + ((size_t)b * Cn + h * HD) * Pn;
    const float* kb = g_k + ((size_t)b * Cn + h * HD) * Pn;
    const float* vb = g_v + ((size_t)b * Cn + h * HD) * Pn;

    float q0[32], q1[32], o0[32], o1[32];
    #pragma unroll
    for (int d = 0; d < 32; d++) {
        q0[d] = qb[(size_t)d * Pn + r0] * scale;
        q1[d] = qb[(size_t)d * Pn + r1] * scale;
        o0[d] = 0.0f; o1[d] = 0.0f;
    }
    float m0 = -1e30f, m1 = -1e30f, l0 = 0.0f, l1 = 0.0f;

    __shared__ __align__(16) float sK[16][36];
    __shared__ __align__(16) float sV[16][36];

    for (int k0 = 0; k0 < Pn; k0 += 16) {
        __syncthreads();
        #pragma unroll
        for (int idx = tid; idx < 512; idx += 128) {
            int kp = idx & 15, d = idx >> 4;
            sK[kp][d] = kb[(size_t)d * Pn + k0 + kp];
            sV[kp][d] = vb[(size_t)d * Pn + k0 + kp];
        }
        __syncthreads();

        float s0[16], s1[16];
        #pragma unroll
        for (int kp = 0; kp < 16; kp++) {
            float a0 = 0.0f, a1 = 0.0f;
            const float4* kr = reinterpret_cast<const float4*>(&sK[kp][0]);
            #pragma unroll
            for (int i = 0; i < 8; i++) {
                float4 kv4 = kr[i];
                a0 += q0[4*i+0] * kv4.x;  a1 += q1[4*i+0] * kv4.x;
                a0 += q0[4*i+1] * kv4.y;  a1 += q1[4*i+1] * kv4.y;
                a0 += q0[4*i+2] * kv4.z;  a1 += q1[4*i+2] * kv4.z;
                a0 += q0[4*i+3] * kv4.w;  a1 += q1[4*i+3] * kv4.w;
            }
            s0[kp] = a0; s1[kp] = a1;
        }
        float tm0 = s0[0], tm1 = s1[0];
        #pragma unroll
        for (int kp = 1; kp < 16; kp++) {
            tm0 = fmaxf(tm0, s0[kp]);
            tm1 = fmaxf(tm1, s1[kp]);
        }
        float mn0 = fmaxf(m0, tm0), mn1 = fmaxf(m1, tm1);
        float c0 = __expf(m0 - mn0), c1 = __expf(m1 - mn1);
        m0 = mn0; m1 = mn1;
        l0 *= c0; l1 *= c1;
        #pragma unroll
        for (int d = 0; d < 32; d++) { o0[d] *= c0; o1[d] *= c1; }
        #pragma unroll
        for (int kp = 0; kp < 16; kp++) {
            float pw0 = __expf(s0[kp] - m0);
            float pw1 = __expf(s1[kp] - m1);
            l0 += pw0; l1 += pw1;
            const float4* vr = reinterpret_cast<const float4*>(&sV[kp][0]);
            #pragma unroll
            for (int i = 0; i < 8; i++) {
                float4 vv = vr[i];
                o0[4*i+0] += pw0 * vv.x;  o1[4*i+0] += pw1 * vv.x;
                o0[4*i+1] += pw0 * vv.y;  o1[4*i+1] += pw1 * vv.y;
                o0[4*i+2] += pw0 * vv.z;  o1[4*i+2] += pw1 * vv.z;
                o0[4*i+3] += pw0 * vv.w;  o1[4*i+3] += pw1 * vv.w;
            }
        }
    }
    float inv0 = 1.0f / l0, inv1 = 1.0f / l1;
    float* ob = g_ao + ((size_t)b * Cn + h * HD) * Pn;
    #pragma unroll
    for (int d = 0; d < 32; d++) {
        ob[(size_t)d * Pn + r0] = o0[d] * inv0;
        ob[(size_t)d * Pn + r1] = o1[d] * inv1;
    }
}

// =====================================================================
extern "C" void kernel_launch(void* const* d_in, const int* in_sizes, int n_in,
                              void* d_out, int out_size)
{
    (void)in_sizes; (void)n_in; (void)out_size;
    const float* query_map = (const float*)d_in[0];
    const float* kv_map    = (const float*)d_in[1];
    const float* Wq        = (const float*)d_in[2];
    const float* Wk        = (const float*)d_in[3];
    const float* Wv        = (const float*)d_in[4];
    const float* Woff1     = (const float*)d_in[5];
    const float* boff1     = (const float*)d_in[6];
    const float* Woff2     = (const float*)d_in[7];
    const float* boff2     = (const float*)d_in[8];
    const float* Wout      = (const float*)d_in[9];
    const float* bout      = (const float*)d_in[10];
    float* out = (float*)d_out;

    float *pq, *pkvs, *pk, *pv, *pao;
    cudaGetSymbolAddress((void**)&pq,   g_q);
    cudaGetSymbolAddress((void**)&pkvs, g_kvs);
    cudaGetSymbolAddress((void**)&pk,   g_k);
    cudaGetSymbolAddress((void**)&pv,   g_v);
    cudaGetSymbolAddress((void**)&pao,  g_ao);

    // 1) q = Wq @ query_map
    gemm_kernel<<<dim3(16, 4, 8), 256>>>(Wq, query_map, nullptr, pq, 256);
    // 2) h1 = relu(conv3x3(q) + boff1)   (implicit GEMM, K=2304)
    conv_kernel<<<dim3(16, 2, 8), 256>>>(Woff1, boff1);
    // 3) offsets (only channels 0,1 needed)
    offs_kernel<<<dim3(4, 8), 256>>>(Woff2, boff2);
    // 4) bilinear sample of kv_map
    samp_kernel<<<dim3(4, 8, 8), 256>>>(kv_map);
    // 5) k, v projections of sampled kv
    gemm_kernel<<<dim3(16, 4, 8), 256>>>(Wk, pkvs, nullptr, pk, 256);
    gemm_kernel<<<dim3(16, 4, 8), 256>>>(Wv, pkvs, nullptr, pv, 256);
    // 6) attention
    attn_kernel<<<dim3(4, 64), 128>>>();
    // 7) out = Wout @ attn_out + bout
    gemm_kernel<<<dim3(16, 4, 8), 256>>>(Wout, pao, bout, out, 256);
}